// round 12
// baseline (speedup 1.0000x reference)
#include <cuda_runtime.h>
#include <cuda_fp16.h>
#include <math.h>

#define NN  100000
#define EE  1600000
#define C   64
#define OC  16
#define CAP 64          // max non-self neighbors per node (Poisson(16): P(>64)~e^-40)

// ---------------- device scratch (no allocations allowed) ----------------
__device__ int   g_fill[NN];                      // neighbor count (excl. self)
__device__ __align__(256) int g_col[(size_t)NN * CAP];   // sentinel-padded bucket CSR
__device__ int   g_is64;                          // edge dtype flag
// fp16 feature buffers + one dummy zero row at index NN
__device__ __align__(256) __half g_bufA[(size_t)(NN + 1) * C];
__device__ __align__(256) __half g_bufB[(size_t)(NN + 1) * C];

union HU { uint4 u; __half2 h[4]; };

__device__ __forceinline__ int edge_src(const void* ei, int e) {
    if (g_is64) return (int)((const long long*)ei)[e];
    return ((const int*)ei)[e];
}
__device__ __forceinline__ int edge_dst(const void* ei, int e) {
    if (g_is64) return (int)((const long long*)ei)[EE + e];
    return ((const int*)ei)[EE + e];
}

// ---------------- init: counters, sentinel CSR, dummy rows, dtype ----------
__global__ void k_init(const unsigned* __restrict__ ei) {
    int i = blockIdx.x * blockDim.x + threadIdx.x;
    if (i < NN * (CAP / 4))
        reinterpret_cast<int4*>(g_col)[i] = make_int4(NN, NN, NN, NN);
    if (i < NN) g_fill[i] = 0;
    if (i < 8) {   // zero dummy rows: 64 halves = 8 uint4
        reinterpret_cast<uint4*>(g_bufA + (size_t)NN * C)[i] = make_uint4(0,0,0,0);
        reinterpret_cast<uint4*>(g_bufB + (size_t)NN * C)[i] = make_uint4(0,0,0,0);
    }
    if (i == 0) {
        int is64 = 1;
        for (int t = 0; t < 64; t++)
            if (ei[2 * t + 1] != 0u) { is64 = 0; break; }
        g_is64 = is64;
    }
}

// ---------------- single-pass bucket fill ----------------
__global__ void k_fill(const void* __restrict__ ei) {
    int e = blockIdx.x * blockDim.x + threadIdx.x;
    if (e < EE) {
        int d = edge_dst(ei, e);
        int s = edge_src(ei, e);
        if ((unsigned)d < NN && (unsigned)s < NN) {
            int p = atomicAdd(&g_fill[d], 1);
            if (p < CAP) g_col[(size_t)d * CAP + p] = s;
        }
    }
}

// ---------------- octet-gather aggregation core ----------------
// Warp handles 4 nodes. One LDG.128 gathers 4 rows (one per lane-octet).
// Returns per-lane fp32 partial sums for channels (lane&7)*8..+8, fully
// octet-reduced; every lane ends with the complete sum for its 8 channels.
__device__ __forceinline__ void agg4_oct(const __half* __restrict__ G, int lane,
                                         int node0, float2 (&acc)[4][4], int (&degv)[4]) {
    int oct  = lane >> 3;
    int cidx = lane & 7;
    float m0 = (oct == 0) ? 1.f : 0.f;

    int cnt[4];
    const int* cols[4];
    #pragma unroll
    for (int rr = 0; rr < 4; rr++) {
        int node = node0 + rr;
        int d = g_fill[node];
        degv[rr] = d;
        cnt[rr] = d < CAP ? d : CAP;
        cols[rr] = g_col + (size_t)node * CAP;
        // self row: all octets load (broadcast line), only octet 0 keeps it
        HU sv; sv.u = __ldcg(reinterpret_cast<const uint4*>(G + (size_t)node * C) + cidx);
        #pragma unroll
        for (int k = 0; k < 4; k++) {
            float2 f = __half22float2(sv.h[k]);
            acc[rr][k].x = m0 * f.x;
            acc[rr][k].y = m0 * f.y;
        }
    }
    int mxc = max(max(cnt[0], cnt[1]), max(cnt[2], cnt[3]));

    for (int e = 0; e < mxc; e += 4) {
        #pragma unroll
        for (int rr = 0; rr < 4; rr++) {
            int4 j4 = *reinterpret_cast<const int4*>(cols[rr] + e);
            int j = (oct == 0) ? j4.x : (oct == 1) ? j4.y : (oct == 2) ? j4.z : j4.w;
            HU v; v.u = __ldcg(reinterpret_cast<const uint4*>(G + (size_t)j * C) + cidx);
            #pragma unroll
            for (int k = 0; k < 4; k++) {
                float2 f = __half22float2(v.h[k]);
                acc[rr][k].x += f.x;
                acc[rr][k].y += f.y;
            }
        }
    }

    // reduce across octets: lanes l, l+8, l+16, l+24 hold same channels
    #pragma unroll
    for (int rr = 0; rr < 4; rr++)
        #pragma unroll
        for (int k = 0; k < 4; k++) {
            acc[rr][k].x += __shfl_xor_sync(0xffffffffu, acc[rr][k].x, 8);
            acc[rr][k].y += __shfl_xor_sync(0xffffffffu, acc[rr][k].y, 8);
            acc[rr][k].x += __shfl_xor_sync(0xffffffffu, acc[rr][k].x, 16);
            acc[rr][k].y += __shfl_xor_sync(0xffffffffu, acc[rr][k].y, 16);
        }
}

// ---------------- layer-1 GEMM: G1 = dinv * (x @ W1) -> g_bufA (fp16) -------
__global__ void k_gemm_scale(const float* __restrict__ in,
                             const float* __restrict__ W) {
    __shared__ __align__(16) float xs[32][68];
    __shared__ __align__(16) float Ws[C][C];
    int tid  = threadIdx.x;
    int row0 = blockIdx.x * 32;

    for (int i4 = tid; i4 < 32 * 16; i4 += 256) {
        float4 v = reinterpret_cast<const float4*>(in + (size_t)row0 * C)[i4];
        *reinterpret_cast<float4*>(&xs[i4 >> 4][(i4 & 15) * 4]) = v;
    }
    for (int i4 = tid; i4 < 16 * C; i4 += 256)
        reinterpret_cast<float4*>(&Ws[0][0])[i4] =
            reinterpret_cast<const float4*>(W)[i4];
    __syncthreads();

    int n  = tid >> 3;
    int c0 = (tid & 7) * 8;
    float acc[8];
    #pragma unroll
    for (int j = 0; j < 8; j++) acc[j] = 0.f;

    #pragma unroll
    for (int k = 0; k < C; k++) {
        float xv = xs[n][k];
        float4 w0 = *reinterpret_cast<const float4*>(&Ws[k][c0]);
        float4 w1 = *reinterpret_cast<const float4*>(&Ws[k][c0 + 4]);
        acc[0] += xv * w0.x; acc[1] += xv * w0.y;
        acc[2] += xv * w0.z; acc[3] += xv * w0.w;
        acc[4] += xv * w1.x; acc[5] += xv * w1.y;
        acc[6] += xv * w1.z; acc[7] += xv * w1.w;
    }

    float dv = rsqrtf((float)(g_fill[row0 + n] + 1));
    HU P;
    P.h[0] = __floats2half2_rn(acc[0]*dv, acc[1]*dv);
    P.h[1] = __floats2half2_rn(acc[2]*dv, acc[3]*dv);
    P.h[2] = __floats2half2_rn(acc[4]*dv, acc[5]*dv);
    P.h[3] = __floats2half2_rn(acc[6]*dv, acc[7]*dv);
    *reinterpret_cast<uint4*>(g_bufA + (size_t)(row0 + n) * C + c0) = P.u;
}

// ---------------- fused agg(L1) + relu + GEMM(W2) + scale -> g_bufB ---------
__global__ void k_agg_gemm(const float* __restrict__ bias,
                           const float* __restrict__ W2) {
    __shared__ __align__(16) float xs[32][68];
    __shared__ __align__(16) float Ws[C][C];
    int tid  = threadIdx.x;
    int warp = tid >> 5;
    int lane = tid & 31;
    int cidx = lane & 7;
    int row0 = blockIdx.x * 32;

    for (int i4 = tid; i4 < 16 * C; i4 += 256)
        reinterpret_cast<float4*>(&Ws[0][0])[i4] =
            reinterpret_cast<const float4*>(W2)[i4];

    float2 acc[4][4]; int degv[4];
    agg4_oct(g_bufA, lane, row0 + warp * 4, acc, degv);

    // bias chunk for this lane's 8 channels
    float4 ba = __ldg(reinterpret_cast<const float4*>(bias + cidx * 8));
    float4 bb = __ldg(reinterpret_cast<const float4*>(bias + cidx * 8 + 4));

    if (lane < 8) {
        #pragma unroll
        for (int rr = 0; rr < 4; rr++) {
            float dv = rsqrtf((float)(degv[rr] + 1));
            float* xr = &xs[warp * 4 + rr][cidx * 8];
            xr[0] = fmaxf(fmaf(dv, acc[rr][0].x, ba.x), 0.f);
            xr[1] = fmaxf(fmaf(dv, acc[rr][0].y, ba.y), 0.f);
            xr[2] = fmaxf(fmaf(dv, acc[rr][1].x, ba.z), 0.f);
            xr[3] = fmaxf(fmaf(dv, acc[rr][1].y, ba.w), 0.f);
            xr[4] = fmaxf(fmaf(dv, acc[rr][2].x, bb.x), 0.f);
            xr[5] = fmaxf(fmaf(dv, acc[rr][2].y, bb.y), 0.f);
            xr[6] = fmaxf(fmaf(dv, acc[rr][3].x, bb.z), 0.f);
            xr[7] = fmaxf(fmaf(dv, acc[rr][3].y, bb.w), 0.f);
        }
    }
    __syncthreads();

    int n  = tid >> 3;
    int c0 = (tid & 7) * 8;
    float gac[8];
    #pragma unroll
    for (int j = 0; j < 8; j++) gac[j] = 0.f;

    #pragma unroll
    for (int k = 0; k < C; k++) {
        float xv = xs[n][k];
        float4 w0 = *reinterpret_cast<const float4*>(&Ws[k][c0]);
        float4 w1 = *reinterpret_cast<const float4*>(&Ws[k][c0 + 4]);
        gac[0] += xv * w0.x; gac[1] += xv * w0.y;
        gac[2] += xv * w0.z; gac[3] += xv * w0.w;
        gac[4] += xv * w1.x; gac[5] += xv * w1.y;
        gac[6] += xv * w1.z; gac[7] += xv * w1.w;
    }

    float dv = rsqrtf((float)(g_fill[row0 + n] + 1));
    HU P;
    P.h[0] = __floats2half2_rn(gac[0]*dv, gac[1]*dv);
    P.h[1] = __floats2half2_rn(gac[2]*dv, gac[3]*dv);
    P.h[2] = __floats2half2_rn(gac[4]*dv, gac[5]*dv);
    P.h[3] = __floats2half2_rn(gac[6]*dv, gac[7]*dv);
    *reinterpret_cast<uint4*>(g_bufB + (size_t)(row0 + n) * C + c0) = P.u;
}

// ---------------- fused agg(L2) + relu + FC + log_softmax -> out ------------
__global__ void k_agg_final(const float* __restrict__ b2,
                            const float* __restrict__ Wfc,
                            const float* __restrict__ bfc,
                            float* __restrict__ out) {
    __shared__ __align__(16) float Wt[OC][C];   // Wt[c][k] = Wfc[k][c]
    __shared__ float bs[OC];
    int tid = threadIdx.x;
    for (int i = tid; i < C * OC; i += 256) {
        int k = i >> 4, c = i & 15;
        Wt[c][k] = Wfc[i];
    }
    if (tid < OC) bs[tid] = bfc[tid];
    __syncthreads();

    int warp = tid >> 5;
    int lane = tid & 31;
    int cidx = lane & 7;
    int node0 = blockIdx.x * 32 + warp * 4;

    float2 acc[4][4]; int degv[4];
    agg4_oct(g_bufB, lane, node0, acc, degv);

    float4 ba = __ldg(reinterpret_cast<const float4*>(b2 + cidx * 8));
    float4 bb = __ldg(reinterpret_cast<const float4*>(b2 + cidx * 8 + 4));

    #pragma unroll
    for (int rr = 0; rr < 4; rr++) {
        float dv = rsqrtf((float)(degv[rr] + 1));
        float h[8];
        h[0] = fmaxf(fmaf(dv, acc[rr][0].x, ba.x), 0.f);
        h[1] = fmaxf(fmaf(dv, acc[rr][0].y, ba.y), 0.f);
        h[2] = fmaxf(fmaf(dv, acc[rr][1].x, ba.z), 0.f);
        h[3] = fmaxf(fmaf(dv, acc[rr][1].y, ba.w), 0.f);
        h[4] = fmaxf(fmaf(dv, acc[rr][2].x, bb.x), 0.f);
        h[5] = fmaxf(fmaf(dv, acc[rr][2].y, bb.y), 0.f);
        h[6] = fmaxf(fmaf(dv, acc[rr][3].x, bb.z), 0.f);
        h[7] = fmaxf(fmaf(dv, acc[rr][3].y, bb.w), 0.f);

        float logit = 0.f;
        #pragma unroll
        for (int c = 0; c < OC; c++) {
            const float* wr = &Wt[c][cidx * 8];
            float4 wa = *reinterpret_cast<const float4*>(wr);
            float4 wb = *reinterpret_cast<const float4*>(wr + 4);
            float p = h[0]*wa.x + h[1]*wa.y + h[2]*wa.z + h[3]*wa.w
                    + h[4]*wb.x + h[5]*wb.y + h[6]*wb.z + h[7]*wb.w;
            p += __shfl_xor_sync(0xffffffffu, p, 1);
            p += __shfl_xor_sync(0xffffffffu, p, 2);
            p += __shfl_xor_sync(0xffffffffu, p, 4);
            if ((lane & 15) == c) logit = p + bs[c];
        }
        // lanes 0-15 hold logits[lane&15] (16-31 mirror); 16-wide softmax
        float mx = logit;
        #pragma unroll
        for (int off = 8; off; off >>= 1)
            mx = fmaxf(mx, __shfl_xor_sync(0xffffffffu, mx, off));
        float ex = expf(logit - mx);
        float sm = ex;
        #pragma unroll
        for (int off = 8; off; off >>= 1)
            sm += __shfl_xor_sync(0xffffffffu, sm, off);
        if (lane < OC)
            out[(size_t)(node0 + rr) * OC + lane] = logit - mx - logf(sm);
    }
}

// ---------------- launch (5 launches; ncu captures launch #4) ---------------
extern "C" void kernel_launch(void* const* d_in, const int* in_sizes, int n_in,
                              void* d_out, int out_size) {
    const float* x   = (const float*)d_in[0];
    const void*  ei  = d_in[1];
    const float* W1  = (const float*)d_in[2];
    const float* b1  = (const float*)d_in[3];
    const float* W2  = (const float*)d_in[4];
    const float* b2  = (const float*)d_in[5];
    const float* Wfc = (const float*)d_in[6];
    const float* bfc = (const float*)d_in[7];
    float* out = (float*)d_out;

    const int TB = 256;
    const int gI = (NN * (CAP / 4) + TB - 1) / TB;   // covers sentinel fill
    const int gE = (EE + TB - 1) / TB;
    const int gG = NN / 32;                           // 3125 (32 nodes/block)

    k_init<<<gI, TB>>>((const unsigned*)ei);            // 1
    k_fill<<<gE, TB>>>(ei);                              // 2
    k_gemm_scale<<<gG, TB>>>(x, W1);                     // 3
    k_agg_gemm<<<gG, TB>>>(b1, W2);                      // 4  (ncu target)
    k_agg_final<<<gG, TB>>>(b2, Wfc, bfc, out);          // 5
}